// round 17
// baseline (speedup 1.0000x reference)
#include <cuda_runtime.h>
#include <cuda_fp16.h>
#include <cstdint>

// ---------------- problem constants ----------------
#define MTOT 16384      // B*S
#define NTOT 4096       // OUT
#define KTOT 4096       // IN
#define KF   512        // N_ADP * RANK
#define RANK 64

// ---------------- device scratch (static; no runtime alloc) ----------------
__device__ __half g_xh[(size_t)MTOT * KTOT];     // fp16(x)
__device__ __half g_wh[(size_t)NTOT * KTOT];     // fp16(Weff)
__device__ __half g_uh[(size_t)NTOT * KF];       // fp16(U)
__device__ __half g_dh[(size_t)KTOT * KF];       // fp16(downs^T)

// ---------------- helpers ----------------
__device__ __forceinline__ uint32_t smem_u32(const void* p) {
    uint32_t a;
    asm("{ .reg .u64 t; cvta.to.shared.u64 t, %1; cvt.u32.u64 %0, t; }" : "=r"(a) : "l"(p));
    return a;
}
__device__ __forceinline__ void cp16(uint32_t dst, const void* src) {
    asm volatile("cp.async.cg.shared.global [%0], [%1], 16;" :: "r"(dst), "l"(src));
}
#define CP_COMMIT()  asm volatile("cp.async.commit_group;" ::: "memory")
#define CP_WAIT2()   asm volatile("cp.async.wait_group 2;" ::: "memory")

__device__ __forceinline__ void ldsm4(uint32_t r[4], uint32_t addr) {
    asm volatile("ldmatrix.sync.aligned.m8n8.x4.shared.b16 {%0,%1,%2,%3}, [%4];"
                 : "=r"(r[0]), "=r"(r[1]), "=r"(r[2]), "=r"(r[3]) : "r"(addr));
}
__device__ __forceinline__ void mma16816(float c[4], const uint32_t a[4], const uint32_t b0,
                                         const uint32_t b1) {
    asm volatile(
        "mma.sync.aligned.m16n8k16.row.col.f32.f16.f16.f32 "
        "{%0,%1,%2,%3}, {%4,%5,%6,%7}, {%8,%9}, {%0,%1,%2,%3};"
        : "+f"(c[0]), "+f"(c[1]), "+f"(c[2]), "+f"(c[3])
        : "r"(a[0]), "r"(a[1]), "r"(a[2]), "r"(a[3]), "r"(b0), "r"(b1));
}

// ---------------- prep kernels ----------------
__global__ void build_u(const float* __restrict__ ups,
                        const float* __restrict__ mags,
                        const float* __restrict__ scales) {
    int idx = blockIdx.x * blockDim.x + threadIdx.x;
    int o = idx >> 9;
    int k = idx & 511;
    int n = k >> 6;
    int r = k & 63;
    float v = ups[((size_t)n * NTOT + o) * RANK + r] * mags[n * NTOT + o] * scales[n];
    g_uh[idx] = __float2half_rn(v);
}

__global__ void downsT_h(const float* __restrict__ downs) {
    __shared__ float t[32][33];
    const int i0 = blockIdx.x * 32;
    const int k0 = blockIdx.y * 32;
    const int tx = threadIdx.x & 31;
    const int ty = threadIdx.x >> 5;
#pragma unroll
    for (int r = 0; r < 4; r++) {
        int kr = ty + r * 8;
        t[kr][tx] = downs[(size_t)(k0 + kr) * KTOT + i0 + tx];
    }
    __syncthreads();
#pragma unroll
    for (int r = 0; r < 4; r++) {
        int ir = ty + r * 8;
        g_dh[(size_t)(i0 + ir) * KF + k0 + tx] = __float2half_rn(t[tx][ir]);
    }
}

__global__ void split_x(const float* __restrict__ x) {
    size_t i = ((size_t)blockIdx.x * blockDim.x + threadIdx.x) * 8;
    float4 a = *(const float4*)(x + i);
    float4 c = *(const float4*)(x + i + 4);
    float vs[8] = {a.x, a.y, a.z, a.w, c.x, c.y, c.z, c.w};
    unsigned short hs[8];
#pragma unroll
    for (int j = 0; j < 8; j++) hs[j] = __half_as_ushort(__float2half_rn(vs[j]));
    uint4 hv;
    hv.x = hs[0] | ((uint32_t)hs[1] << 16); hv.y = hs[2] | ((uint32_t)hs[3] << 16);
    hv.z = hs[4] | ((uint32_t)hs[5] << 16); hv.w = hs[6] | ((uint32_t)hs[7] << 16);
    *(uint4*)((char*)g_xh + i * 2) = hv;
}

// ---------------- HMMA GEMM: single-term fp16, fp32 accum ----------------
// C = A.B^T   (A: [M][K] fp16, B: [4096][K] fp16, both K-major)
// 256 threads, 8 warps in 4(m) x 2(n), warp tile 64x64. BK=64, 4 stages,
// one __syncthreads per stage. Halved LDSM traffic vs 64x32 warp tiles.
// MODE 0: outf = C + add[n]              (bias)
// MODE 1: outh = fp16(C + add[m*4096+n]) (fold: +W, fp16 result)
#define BM 256
#define BN 128
#define BK 64
#define STAGES 4
#define ASTAGE (BM * 128)                 // 128 B per row (64 fp16)
#define BSTAGE (BN * 128)
#define STAGE_BYTES (ASTAGE + BSTAGE)     // 49152
#define SMEM_BYTES (STAGES * STAGE_BYTES) // 196608

template <int MODE>
__global__ __launch_bounds__(256, 1)
void gemm_mma(const __half* __restrict__ A, const __half* __restrict__ B,
              const float* __restrict__ add,
              float* __restrict__ outf, __half* __restrict__ outh,
              int K) {
    extern __shared__ char smem[];
    const uint32_t sbase = smem_u32(smem);
    const int tid  = threadIdx.x;
    const int lane = tid & 31;
    const int wid  = tid >> 5;       // 0..7
    const int wm   = wid & 3;        // m tile of 64
    const int wn   = wid >> 2;       // n tile of 64
    const int bm   = blockIdx.y * BM;
    const int bn   = blockIdx.x * BN;
    const int nstage = K / BK;

    // ---- stage loader (cp.async), 256 threads ----
    // A: 256 rows x 8 chunks(16B) = 2048 -> 8 per thread (one full row)
    // B: 128 rows x 8 chunks(16B) = 1024 -> 4 per thread
    const int arow = tid;
    const int brow = tid >> 1;
    const int bj0  = (tid & 1) * 4;
    const char* srcA = (const char*)(A + (size_t)(bm + arow) * K);
    const char* srcB = (const char*)(B + (size_t)(bn + brow) * K);

    auto load_stage = [&](int s, int k0) {
        const uint32_t sA = sbase + (uint32_t)s * STAGE_BYTES;
        const uint32_t sB = sA + ASTAGE;
        const uint32_t abase = sA + (uint32_t)arow * 128;
        const int ax = arow & 7;
#pragma unroll
        for (int j = 0; j < 8; j++)
            cp16(abase + (uint32_t)((j ^ ax) << 4), srcA + (size_t)k0 * 2 + (size_t)j * 16);
        const uint32_t bbase = sB + (uint32_t)brow * 128;
        const int bx = brow & 7;
#pragma unroll
        for (int jj = 0; jj < 4; jj++) {
            int j = bj0 + jj;
            cp16(bbase + (uint32_t)((j ^ bx) << 4), srcB + (size_t)k0 * 2 + (size_t)j * 16);
        }
    };

    float acc[4][8][4];
#pragma unroll
    for (int i = 0; i < 4; i++)
#pragma unroll
        for (int j = 0; j < 8; j++)
#pragma unroll
            for (int c = 0; c < 4; c++) acc[i][j][c] = 0.f;

    // prologue: stages 0..2
    load_stage(0, 0);
    CP_COMMIT();
    load_stage(1, BK);
    CP_COMMIT();
    load_stage(2, 2 * BK);
    CP_COMMIT();

    // per-thread ldmatrix address components
    const int arowf = wm * 64 + (lane & 15);                       // + mi*16
    const int ahalf = lane >> 4;                                   // k parity chunk
    const int browf = wn * 64 + ((lane >> 4) << 3) + (lane & 7);   // + p*16
    const int bpar  = (lane >> 3) & 1;

    for (int t = 0; t < nstage; ++t) {
        CP_WAIT2();
        __syncthreads();    // single barrier: compute(t-1) done before its buffer
                            // is overwritten by the load below

        if (t + 3 < nstage) load_stage((t + 3) % STAGES, (t + 3) * BK);
        CP_COMMIT();

        const uint32_t sA = sbase + (uint32_t)((t % STAGES) * STAGE_BYTES);
        const uint32_t sB = sA + ASTAGE;

#pragma unroll
        for (int ks = 0; ks < 4; ++ks) {
            // B fragments for this warp's 64 columns (4 ldsm4, n = 4*16)
            uint32_t bh[4][4];
#pragma unroll
            for (int p = 0; p < 4; ++p) {
                int r = browf + p * 16;
                uint32_t off = (uint32_t)r * 128 + (uint32_t)(ks * 2 + bpar) * 16;
                ldsm4(bh[p], sB + (off ^ ((off >> 3) & 0x70)));
            }
#pragma unroll
            for (int mi = 0; mi < 4; ++mi) {
                int r = arowf + mi * 16;
                uint32_t off = (uint32_t)r * 128 + (uint32_t)(ks * 2 + ahalf) * 16;
                uint32_t ah[4];
                ldsm4(ah, sA + (off ^ ((off >> 3) & 0x70)));
#pragma unroll
                for (int p = 0; p < 4; ++p) {
                    mma16816(acc[mi][2 * p],     ah, bh[p][0], bh[p][1]);
                    mma16816(acc[mi][2 * p + 1], ah, bh[p][2], bh[p][3]);
                }
            }
        }
    }

    // ---- epilogue ----
    const int r0 = bm + wm * 64 + (lane >> 2);
    const int c0 = bn + wn * 64 + (lane & 3) * 2;
#pragma unroll
    for (int mi = 0; mi < 4; ++mi) {
#pragma unroll
        for (int nj = 0; nj < 8; ++nj) {
            int row = r0 + mi * 16;
            int col = c0 + nj * 8;
            if (MODE == 0) {
                float2 bv = *(const float2*)(add + col);
                float2 v0 = make_float2(acc[mi][nj][0] + bv.x, acc[mi][nj][1] + bv.y);
                float2 v1 = make_float2(acc[mi][nj][2] + bv.x, acc[mi][nj][3] + bv.y);
                *(float2*)(outf + (size_t)row * 4096 + col)       = v0;
                *(float2*)(outf + (size_t)(row + 8) * 4096 + col) = v1;
            } else {
                float2 w0 = *(const float2*)(add + (size_t)row * 4096 + col);
                float2 w1 = *(const float2*)(add + (size_t)(row + 8) * 4096 + col);
                unsigned short hh[4];
                hh[0] = __half_as_ushort(__float2half_rn(acc[mi][nj][0] + w0.x));
                hh[1] = __half_as_ushort(__float2half_rn(acc[mi][nj][1] + w0.y));
                hh[2] = __half_as_ushort(__float2half_rn(acc[mi][nj][2] + w1.x));
                hh[3] = __half_as_ushort(__float2half_rn(acc[mi][nj][3] + w1.y));
                *(uint32_t*)((char*)outh + ((size_t)row * 4096 + col) * 2) =
                    hh[0] | ((uint32_t)hh[1] << 16);
                *(uint32_t*)((char*)outh + ((size_t)(row + 8) * 4096 + col) * 2) =
                    hh[2] | ((uint32_t)hh[3] << 16);
            }
        }
    }
}

// ---------------- launch ----------------
extern "C" void kernel_launch(void* const* d_in, const int* in_sizes, int n_in,
                              void* d_out, int out_size) {
    const float* x      = (const float*)d_in[0];
    const float* W      = (const float*)d_in[1];
    const float* b      = (const float*)d_in[2];
    const float* downs  = (const float*)d_in[3];
    const float* ups    = (const float*)d_in[4];
    const float* mags   = (const float*)d_in[5];
    const float* scales = (const float*)d_in[6];
    float* out = (float*)d_out;

    __half *xh, *wh, *uh, *dh;
    cudaGetSymbolAddress((void**)&xh, g_xh);
    cudaGetSymbolAddress((void**)&wh, g_wh);
    cudaGetSymbolAddress((void**)&uh, g_uh);
    cudaGetSymbolAddress((void**)&dh, g_dh);

    cudaFuncSetAttribute(gemm_mma<0>, cudaFuncAttributeMaxDynamicSharedMemorySize, SMEM_BYTES);
    cudaFuncSetAttribute(gemm_mma<1>, cudaFuncAttributeMaxDynamicSharedMemorySize, SMEM_BYTES);

    // 1) prep
    build_u<<<(NTOT * KF) / 256, 256>>>(ups, mags, scales);
    downsT_h<<<dim3(KTOT / 32, KF / 32), 256>>>(downs);
    split_x<<<(size_t)MTOT * KTOT / 8 / 256, 256>>>(x);

    // 2) fold: wh = fp16(W + uh.dh^T)
    gemm_mma<1><<<dim3(NTOT / BN, NTOT / BM), 256, SMEM_BYTES>>>(
        uh, dh, W, nullptr, wh, KF);

    // 3) main: out = xh.wh^T + bias
    gemm_mma<0><<<dim3(NTOT / BN, MTOT / BM), 256, SMEM_BYTES>>>(
        xh, wh, b, out, nullptr, KTOT);
}